// round 14
// baseline (speedup 1.0000x reference)
#include <cuda_runtime.h>
#include <math.h>

// ---------------- problem constants ----------------
#define Bb   16
#define Nn   785
#define Cc   768
#define Hh   12
#define Dd   64
#define Ss   79          // 1 CLS + 78 selected patches
#define NPp  784
#define KSEL 78
#define HSTR (Nn*Nn)          // head stride in attention_history
#define BSTR (Hh*Nn*Nn)       // batch stride
#define LSTR (Bb*Hh*Nn*Nn)    // layer stride
#define OUT1 (Bb*Nn*Cc)       // 9,646,080
#define OUT2 (Bb*Hh*Ss*Nn)    // 11,906,880
#define SCALE_F 0.125f        // 64^-0.5

// ---------------- device scratch (no allocations allowed) ----------------
__device__ float  g_e2[Bb*Nn];        // layer-1 row-0 e-values (pre-normalization)
__device__ float  g_v2[Bb*Nn];        // a2 row 0 normalized (ref-bit fp32)
__device__ float  g_r1[Bb*Nn];        // layer-0 row-normalizers
__device__ float  g_r2[Bb];           // layer-1 row-0 normalizer
__device__ float  g_E  [(size_t)Bb*Nn*Nn];  // layer-0 e-matrix (0.5*mean_h + 0.5*I)
__device__ float  g_scoref[Bb*Nn];    // fp32 scores (ref-matching rounding)
__device__ int    g_sel[Bb*Ss];       // selected token indices
__device__ float  g_k  [(size_t)Bb*Nn*Cc];
__device__ float  g_v  [(size_t)Bb*Nn*Cc];
__device__ float  g_qloc[Bb*Ss*Cc];
__device__ float  g_q  [Bb*Ss*Cc];
__device__ float  g_av [Bb*Ss*Cc];
__device__ float  g_o  [Bb*Ss*Cc];
__device__ float  g_attn_scratch[(size_t)Bb*Hh*Ss*Nn];

// ---------------- layer-0 E matrix: E[b,j,k] = fp32(0.5*mean_h + 0.5*I) ----
__global__ void build_E_kernel(const float* __restrict__ AH) {
    int j = blockIdx.x, b = blockIdx.y;
    const float* base = AH + (long)b*BSTR + (long)j*Nn;   // layer 0, row j
    float* erow = g_E + ((size_t)b*Nn + j)*Nn;
    for (int k = threadIdx.x; k < Nn; k += 256) {
        const float* p = base + k;
        float sh = 0.f;
        #pragma unroll
        for (int h = 0; h < Hh; h++) sh = __fadd_rn(sh, p[(long)h*HSTR]);
        float m = __fdiv_rn(sh, 12.0f);
        float e = __fmul_rn(0.5f, m);            // exact
        if (j == k) e = __fadd_rn(e, 0.5f);
        erow[k] = e;
    }
}

// ---------------- layer-1 row-0 e-values ----------------
__global__ void build_e2_kernel(const float* __restrict__ AH) {
    int b = blockIdx.y;
    int j = blockIdx.x * 256 + threadIdx.x;
    if (j >= Nn) return;
    const float* base = AH + (long)LSTR + (long)b*BSTR;   // layer 1, row 0
    float sh = 0.f;
    #pragma unroll
    for (int h = 0; h < Hh; h++) sh = __fadd_rn(sh, base[(long)h*HSTR + j]);
    float m = __fdiv_rn(sh, 12.0f);
    float e = __fmul_rn(0.5f, m);
    if (j == 0) e = __fadd_rn(e, 0.5f);
    g_e2[b*Nn + j] = e;
}

// ---------------- row reduction for normalizers (bits are common-mode) ----
__device__ __forceinline__ float warp_shfl_down_sum(float v) {
    v = __fadd_rn(v, __shfl_down_sync(0xffffffffu, v, 16));
    v = __fadd_rn(v, __shfl_down_sync(0xffffffffu, v, 8));
    v = __fadd_rn(v, __shfl_down_sync(0xffffffffu, v, 4));
    v = __fadd_rn(v, __shfl_down_sync(0xffffffffu, v, 2));
    v = __fadd_rn(v, __shfl_down_sync(0xffffffffu, v, 1));
    return v;
}

__global__ void rowsum_xla_kernel(const float* __restrict__ rows,
                                  float* __restrict__ out, int nrows) {
    int row = blockIdx.x;
    if (row >= nrows) return;
    int t = threadIdx.x;               // 0..1023
    float v = (t < Nn) ? rows[(size_t)row*Nn + t] : 0.f;
    v = warp_shfl_down_sum(v);
    __shared__ float s[32];
    if ((t & 31) == 0) s[t >> 5] = v;
    __syncthreads();
    if (t < 32) {
        float w = s[t];
        w = warp_shfl_down_sum(w);
        if (t == 0) out[row] = w;
    }
}

// ---------------- v2 = e2 / r2 ----------------
__global__ void v2_kernel() {
    int b = blockIdx.y;
    int j = blockIdx.x * 256 + threadIdx.x;
    if (j >= Nn) return;
    g_v2[b*Nn + j] = __fdiv_rn(g_e2[b*Nn + j], g_r2[b]);
}

// ---------------- scores: 2-lane interleaved (LLVM VF=2 reduction) --------
// Vector loop over pairs (0,1),(2,3),...,(782,783): lane0 accumulates even
// j, lane1 odd j (392 fma terms each). Horizontal combine acc0+acc1 (IEEE
// add commutative => unambiguous), then scalar-remainder tail j=784 fma'd
// onto the combined sum.
__global__ void score_chain_kernel() {
    int b = blockIdx.y;
    int k = blockIdx.x * 128 + threadIdx.x;
    if (k >= Nn) return;
    const float* Eb  = g_E + (size_t)b*Nn*Nn;
    const float* r1b = g_r1 + b*Nn;
    const float* v2b = g_v2 + b*Nn;
    float acc0 = 0.f, acc1 = 0.f;
    #pragma unroll 2
    for (int j = 0; j < NPp; j += 2) {          // j = 0..782 step 2 (NPp=784)
        float a0 = __fdiv_rn(Eb[(size_t)j*Nn + k],     r1b[j]);
        float a1 = __fdiv_rn(Eb[(size_t)(j+1)*Nn + k], r1b[j+1]);
        acc0 = __fmaf_rn(v2b[j],   a0, acc0);
        acc1 = __fmaf_rn(v2b[j+1], a1, acc1);
    }
    float c = __fadd_rn(acc0, acc1);            // horizontal reduce
    float at = __fdiv_rn(Eb[(size_t)(Nn-1)*Nn + k], r1b[Nn-1]);
    c = __fmaf_rn(v2b[Nn-1], at, c);            // scalar tail j=784
    g_scoref[b*Nn + k] = c;
}

// ---------------- top-k (fp32 scores, jax.lax.top_k semantics) ------------
__global__ void topk_kernel() {
    int b = blockIdx.x;
    int tid = threadIdx.x;
    __shared__ float sc[NPp];
    __shared__ float red_v[256];
    __shared__ int   red_i[256];
    for (int p = tid; p < NPp; p += 256)
        sc[p] = g_scoref[b*Nn + 1 + p];
    if (tid == 0) g_sel[b*Ss] = 0;   // CLS always first
    __syncthreads();
    for (int it = 0; it < KSEL; it++) {
        float bv = -1.0f; int bi = NPp;
        for (int p = tid; p < NPp; p += 256) {
            float v = sc[p];
            if (v > bv || (v == bv && p < bi)) { bv = v; bi = p; }
        }
        red_v[tid] = bv; red_i[tid] = bi; __syncthreads();
        for (int off = 128; off > 0; off >>= 1) {
            if (tid < off) {
                float ov = red_v[tid+off]; int oi = red_i[tid+off];
                if (ov > red_v[tid] || (ov == red_v[tid] && oi < red_i[tid])) {
                    red_v[tid] = ov; red_i[tid] = oi;
                }
            }
            __syncthreads();
        }
        if (tid == 0) {
            int p = red_i[0];
            g_sel[b*Ss + 1 + it] = p + 1;
            sc[p] = -2.0f;   // scores positive; exclude
        }
        __syncthreads();
    }
}

// ---------------- gather selected x rows (float4) ----------------
__global__ void gather_kernel(const float* __restrict__ x) {
    int s = blockIdx.x, b = blockIdx.y;
    int tok = g_sel[b*Ss + s];
    const float4* src = (const float4*)(x + ((long)b*Nn + tok)*Cc);
    float4* dst = (float4*)(g_qloc + ((long)b*Ss + s)*Cc);
    for (int c = threadIdx.x; c < Cc/4; c += blockDim.x) dst[c] = src[c];
}

// ---------------- generic batched-strided GEMM ----------------
// C[m,n] = alpha * sum_k A[m,k] * B(n,k)  (+ bias[n])
// BT=true : B is [n,k] row-major (NT);  BT=false : B is [k,n] row-major (NN)
template<bool BT>
__global__ void gemm128_kernel(const float* __restrict__ Ag,
                               const float* __restrict__ Bg,
                               float* __restrict__ Cg,
                               int M, int Ncols, int K,
                               int lda, int ldb, int ldc,
                               long sAb, long sAh, long sBb, long sBh,
                               long sCb, long sCh, int Hdim,
                               const float* __restrict__ bias, float alpha)
{
    const int BM = 128, BN = 128, BK = 16;
    int z  = blockIdx.z;
    int zb = z / Hdim, zh = z % Hdim;
    const float* A = Ag + zb*sAb + zh*sAh;
    const float* Bp = Bg + zb*sBb + zh*sBh;
    float* C = Cg + zb*sCb + zh*sCh;
    int m0 = blockIdx.y * BM;
    int n0 = blockIdx.x * BN;

    __shared__ float As[BK][BM];
    __shared__ float Bs[BK][BN];

    int tid = threadIdx.x;
    int tx = tid & 15, ty = tid >> 4;
    float acc[8][8];
    #pragma unroll
    for (int i = 0; i < 8; i++)
        #pragma unroll
        for (int j = 0; j < 8; j++) acc[i][j] = 0.f;

    for (int k0 = 0; k0 < K; k0 += BK) {
        #pragma unroll
        for (int idx = tid; idx < BM*BK; idx += 256) {
            int mm = idx >> 4, kk = idx & 15;
            int gm = m0 + mm, gk = k0 + kk;
            float v = 0.f;
            if (gm < M && gk < K) v = A[(long)gm*lda + gk];
            As[kk][mm] = v;
        }
        #pragma unroll
        for (int idx = tid; idx < BN*BK; idx += 256) {
            int nn, kk;
            if (BT) { nn = idx >> 4; kk = idx & 15; }
            else    { kk = idx >> 7; nn = idx & 127; }
            int gn = n0 + nn, gk = k0 + kk;
            float v = 0.f;
            if (gn < Ncols && gk < K)
                v = BT ? Bp[(long)gn*ldb + gk] : Bp[(long)gk*ldb + gn];
            Bs[kk][nn] = v;
        }
        __syncthreads();
        #pragma unroll
        for (int kk = 0; kk < BK; kk++) {
            float a[8], bb[8];
            #pragma unroll
            for (int i = 0; i < 8; i++) a[i] = As[kk][ty*8 + i];
            #pragma unroll
            for (int j = 0; j < 8; j++) bb[j] = Bs[kk][tx*8 + j];
            #pragma unroll
            for (int i = 0; i < 8; i++)
                #pragma unroll
                for (int j = 0; j < 8; j++) acc[i][j] += a[i]*bb[j];
        }
        __syncthreads();
    }

    #pragma unroll
    for (int i = 0; i < 8; i++) {
        int gm = m0 + ty*8 + i;
        if (gm >= M) continue;
        #pragma unroll
        for (int j = 0; j < 8; j++) {
            int gn = n0 + tx*8 + j;
            if (gn >= Ncols) continue;
            float v = acc[i][j]*alpha;
            if (bias) v += bias[gn];
            C[(long)gm*ldc + gn] = v;
        }
    }
}

// ---------------- softmax over rows of length N ----------------
__global__ void softmax_kernel(float* __restrict__ P) {
    long row = blockIdx.x;
    float* d = P + row*(long)Nn;
    int tid = threadIdx.x;
    __shared__ float red[256];

    float mx = -INFINITY;
    for (int i = tid; i < Nn; i += 256) { float v = d[i]; mx = v > mx ? v : mx; }
    red[tid] = mx; __syncthreads();
    for (int off = 128; off > 0; off >>= 1) {
        if (tid < off && red[tid+off] > red[tid]) red[tid] = red[tid+off];
        __syncthreads();
    }
    mx = red[0]; __syncthreads();

    float sum = 0.f;
    for (int i = tid; i < Nn; i += 256) {
        float e = expf(d[i] - mx);
        d[i] = e;
        sum += e;
    }
    red[tid] = sum; __syncthreads();
    for (int off = 128; off > 0; off >>= 1) {
        if (tid < off) red[tid] += red[tid+off];
        __syncthreads();
    }
    float inv = 1.0f / red[0];
    for (int i = tid; i < Nn; i += 256) d[i] *= inv;
}

// ---------------- zero + scatter ----------------
__global__ void zero_kernel(float4* __restrict__ p, long n4) {
    long i = (long)blockIdx.x * blockDim.x + threadIdx.x;
    if (i < n4) p[i] = make_float4(0.f, 0.f, 0.f, 0.f);
}

__global__ void scatter_kernel(float* __restrict__ out) {
    int s = blockIdx.x, b = blockIdx.y;
    int tok = g_sel[b*Ss + s];
    const float4* src = (const float4*)(g_o + ((long)b*Ss + s)*Cc);
    float4* dst = (float4*)(out + ((long)b*Nn + tok)*Cc);
    for (int c = threadIdx.x; c < Cc/4; c += blockDim.x) dst[c] = src[c];
}

// ---------------- launch ----------------
extern "C" void kernel_launch(void* const* d_in, const int* in_sizes, int n_in,
                              void* d_out, int out_size) {
    const float* x  = (const float*)d_in[0];
    const float* AH = (const float*)d_in[1];
    const float* Wq = (const float*)d_in[2];
    const float* bq = (const float*)d_in[3];
    const float* Wk = (const float*)d_in[4];
    const float* bk = (const float*)d_in[5];
    const float* Wv = (const float*)d_in[6];
    const float* bv = (const float*)d_in[7];
    const float* Wo = (const float*)d_in[8];
    const float* bo = (const float*)d_in[9];
    float* out = (float*)d_out;

    float *pk, *pv, *pqloc, *pq, *pav, *po, *pattn_s, *pE, *pe2, *pr1, *pr2;
    cudaGetSymbolAddress((void**)&pk,      g_k);
    cudaGetSymbolAddress((void**)&pv,      g_v);
    cudaGetSymbolAddress((void**)&pqloc,   g_qloc);
    cudaGetSymbolAddress((void**)&pq,      g_q);
    cudaGetSymbolAddress((void**)&pav,     g_av);
    cudaGetSymbolAddress((void**)&po,      g_o);
    cudaGetSymbolAddress((void**)&pattn_s, g_attn_scratch);
    cudaGetSymbolAddress((void**)&pE,      g_E);
    cudaGetSymbolAddress((void**)&pe2,     g_e2);
    cudaGetSymbolAddress((void**)&pr1,     g_r1);
    cudaGetSymbolAddress((void**)&pr2,     g_r2);

    float* attnP = (out_size >= OUT1 + OUT2) ? (out + OUT1) : pattn_s;

    // ---- rollout (row-0 factorization; 2-lane interleaved score dot) ----
    build_E_kernel<<<dim3(Nn, Bb), 256>>>(AH);
    build_e2_kernel<<<dim3((Nn+255)/256, Bb), 256>>>(AH);
    rowsum_xla_kernel<<<Bb*Nn, 1024>>>(pE, pr1, Bb*Nn);   // r1 rows of E
    rowsum_xla_kernel<<<Bb, 1024>>>(pe2, pr2, Bb);        // r2 rows of e2
    v2_kernel<<<dim3((Nn+255)/256, Bb), 256>>>();
    score_chain_kernel<<<dim3((Nn+127)/128, Bb), 128>>>();
    topk_kernel<<<Bb, 256>>>();
    gather_kernel<<<dim3(Ss, Bb), 256>>>(x);

    // ---- projections: y = x @ W^T + b  (NT GEMMs) ----
    {
        dim3 g(Cc/128, (Bb*Nn + 127)/128, 1);
        gemm128_kernel<true><<<g, 256>>>(x, Wk, pk, Bb*Nn, Cc, Cc, Cc, Cc, Cc,
                                         0,0,0,0,0,0, 1, bk, 1.0f);
        gemm128_kernel<true><<<g, 256>>>(x, Wv, pv, Bb*Nn, Cc, Cc, Cc, Cc, Cc,
                                         0,0,0,0,0,0, 1, bv, 1.0f);
    }
    {
        dim3 g(Cc/128, (Bb*Ss + 127)/128, 1);
        gemm128_kernel<true><<<g, 256>>>(pqloc, Wq, pq, Bb*Ss, Cc, Cc, Cc, Cc, Cc,
                                         0,0,0,0,0,0, 1, bq, 1.0f);
    }

    // ---- logits: attn[b,h,s,n] = SCALE * q . k  (batched NT) ----
    {
        dim3 g((Nn+127)/128, 1, Bb*Hh);
        gemm128_kernel<true><<<g, 256>>>(pq, pk, attnP,
                                         Ss, Nn, Dd,
                                         Cc, Cc, Nn,
                                         (long)Ss*Cc, (long)Dd,
                                         (long)Nn*Cc, (long)Dd,
                                         (long)Hh*Ss*Nn, (long)Ss*Nn, Hh,
                                         nullptr, SCALE_F);
    }

    // ---- softmax rows (this IS the attn_weights output) ----
    softmax_kernel<<<Bb*Hh*Ss, 256>>>(attnP);

    // ---- AV: out[b,h,s,d] = P @ V  (batched NN) ----
    {
        dim3 g(1, 1, Bb*Hh);
        gemm128_kernel<false><<<g, 256>>>(attnP, pv, pav,
                                          Ss, Dd, Nn,
                                          Nn, Cc, Cc,
                                          (long)Hh*Ss*Nn, (long)Ss*Nn,
                                          (long)Nn*Cc, (long)Dd,
                                          (long)Ss*Cc, (long)Dd, Hh,
                                          nullptr, 1.0f);
    }

    // ---- output projection (NT) ----
    {
        dim3 g(Cc/128, (Bb*Ss + 127)/128, 1);
        gemm128_kernel<true><<<g, 256>>>(pav, Wo, po, Bb*Ss, Cc, Cc, Cc, Cc, Cc,
                                         0,0,0,0,0,0, 1, bo, 1.0f);
    }

    // ---- scatter into zeroed token grid ----
    zero_kernel<<<(OUT1/4 + 255)/256, 256>>>((float4*)out, (long)(OUT1/4));
    scatter_kernel<<<dim3(Ss, Bb), 256>>>(out);
}

// round 15
// speedup vs baseline: 1.3535x; 1.3535x over previous
#include <cuda_runtime.h>
#include <math.h>

// ---------------- problem constants ----------------
#define Bb   16
#define Nn   785
#define Cc   768
#define Hh   12
#define Dd   64
#define Ss   79          // 1 CLS + 78 selected patches
#define NPp  784
#define KSEL 78
#define HSTR (Nn*Nn)          // head stride in attention_history
#define BSTR (Hh*Nn*Nn)       // batch stride
#define LSTR (Bb*Hh*Nn*Nn)    // layer stride
#define OUT1 (Bb*Nn*Cc)       // 9,646,080
#define OUT2 (Bb*Hh*Ss*Nn)    // 11,906,880
#define SCALE_F 0.125f        // 64^-0.5

// ---------------- device scratch (no allocations allowed) ----------------
__device__ float  g_e2[Bb*Nn];        // layer-1 row-0 e-values (pre-normalization)
__device__ float  g_v2[Bb*Nn];        // a2 row 0 normalized (ref-bit fp32)
__device__ float  g_r1[Bb*Nn];        // layer-0 row-normalizers
__device__ float  g_r2[Bb];           // layer-1 row-0 normalizer
__device__ float  g_E  [(size_t)Bb*Nn*Nn];  // layer-0 e-matrix (0.5*mean_h + 0.5*I)
__device__ float  g_scoref[Bb*Nn];    // fp32 scores (ref-matching rounding)
__device__ int    g_sel[Bb*Ss];       // selected token indices
__device__ float  g_k  [(size_t)Bb*Nn*Cc];
__device__ float  g_v  [(size_t)Bb*Nn*Cc];
__device__ float  g_qloc[Bb*Ss*Cc];
__device__ float  g_q  [Bb*Ss*Cc];
__device__ float  g_av [Bb*Ss*Cc];
__device__ float  g_o  [Bb*Ss*Cc];
__device__ float  g_attn_scratch[(size_t)Bb*Hh*Ss*Nn];

// ---------------- layer-0 E matrix: E[b,j,k] = fp32(0.5*mean_h + 0.5*I) ----
__global__ void build_E_kernel(const float* __restrict__ AH) {
    int j = blockIdx.x, b = blockIdx.y;
    const float* base = AH + (long)b*BSTR + (long)j*Nn;   // layer 0, row j
    float* erow = g_E + ((size_t)b*Nn + j)*Nn;
    for (int k = threadIdx.x; k < Nn; k += 256) {
        const float* p = base + k;
        float sh = 0.f;
        #pragma unroll
        for (int h = 0; h < Hh; h++) sh = __fadd_rn(sh, p[(long)h*HSTR]);
        float m = __fdiv_rn(sh, 12.0f);
        float e = __fmul_rn(0.5f, m);            // exact
        if (j == k) e = __fadd_rn(e, 0.5f);
        erow[k] = e;
    }
}

// ---------------- layer-1 row-0 e-values ----------------
__global__ void build_e2_kernel(const float* __restrict__ AH) {
    int b = blockIdx.y;
    int j = blockIdx.x * 256 + threadIdx.x;
    if (j >= Nn) return;
    const float* base = AH + (long)LSTR + (long)b*BSTR;   // layer 1, row 0
    float sh = 0.f;
    #pragma unroll
    for (int h = 0; h < Hh; h++) sh = __fadd_rn(sh, base[(long)h*HSTR + j]);
    float m = __fdiv_rn(sh, 12.0f);
    float e = __fmul_rn(0.5f, m);
    if (j == 0) e = __fadd_rn(e, 0.5f);
    g_e2[b*Nn + j] = e;
}

// ---------------- row reduction for normalizers (bits are common-mode) ----
__device__ __forceinline__ float warp_shfl_down_sum(float v) {
    v = __fadd_rn(v, __shfl_down_sync(0xffffffffu, v, 16));
    v = __fadd_rn(v, __shfl_down_sync(0xffffffffu, v, 8));
    v = __fadd_rn(v, __shfl_down_sync(0xffffffffu, v, 4));
    v = __fadd_rn(v, __shfl_down_sync(0xffffffffu, v, 2));
    v = __fadd_rn(v, __shfl_down_sync(0xffffffffu, v, 1));
    return v;
}

__global__ void rowsum_xla_kernel(const float* __restrict__ rows,
                                  float* __restrict__ out, int nrows) {
    int row = blockIdx.x;
    if (row >= nrows) return;
    int t = threadIdx.x;               // 0..1023
    float v = (t < Nn) ? rows[(size_t)row*Nn + t] : 0.f;
    v = warp_shfl_down_sum(v);
    __shared__ float s[32];
    if ((t & 31) == 0) s[t >> 5] = v;
    __syncthreads();
    if (t < 32) {
        float w = s[t];
        w = warp_shfl_down_sum(w);
        if (t == 0) out[row] = w;
    }
}

// ---------------- v2 = e2 / r2 ----------------
__global__ void v2_kernel() {
    int b = blockIdx.y;
    int j = blockIdx.x * 256 + threadIdx.x;
    if (j >= Nn) return;
    g_v2[b*Nn + j] = __fdiv_rn(g_e2[b*Nn + j], g_r2[b]);
}

// ---------------- scores: 2-lane interleaved (LLVM VF=2 reduction) --------
// MATCHES REFERENCE BITS — DO NOT TOUCH.
__global__ void score_chain_kernel() {
    int b = blockIdx.y;
    int k = blockIdx.x * 128 + threadIdx.x;
    if (k >= Nn) return;
    const float* Eb  = g_E + (size_t)b*Nn*Nn;
    const float* r1b = g_r1 + b*Nn;
    const float* v2b = g_v2 + b*Nn;
    float acc0 = 0.f, acc1 = 0.f;
    #pragma unroll 2
    for (int j = 0; j < NPp; j += 2) {          // j = 0..782 step 2 (NPp=784)
        float a0 = __fdiv_rn(Eb[(size_t)j*Nn + k],     r1b[j]);
        float a1 = __fdiv_rn(Eb[(size_t)(j+1)*Nn + k], r1b[j+1]);
        acc0 = __fmaf_rn(v2b[j],   a0, acc0);
        acc1 = __fmaf_rn(v2b[j+1], a1, acc1);
    }
    float c = __fadd_rn(acc0, acc1);            // horizontal reduce
    float at = __fdiv_rn(Eb[(size_t)(Nn-1)*Nn + k], r1b[Nn-1]);
    c = __fmaf_rn(v2b[Nn-1], at, c);            // scalar tail j=784
    g_scoref[b*Nn + k] = c;
}

// ---------------- top-k (fp32 scores, jax.lax.top_k semantics) ------------
__global__ void topk_kernel() {
    int b = blockIdx.x;
    int tid = threadIdx.x;
    __shared__ float sc[NPp];
    __shared__ float red_v[256];
    __shared__ int   red_i[256];
    for (int p = tid; p < NPp; p += 256)
        sc[p] = g_scoref[b*Nn + 1 + p];
    if (tid == 0) g_sel[b*Ss] = 0;   // CLS always first
    __syncthreads();
    for (int it = 0; it < KSEL; it++) {
        float bv = -1.0f; int bi = NPp;
        for (int p = tid; p < NPp; p += 256) {
            float v = sc[p];
            if (v > bv || (v == bv && p < bi)) { bv = v; bi = p; }
        }
        red_v[tid] = bv; red_i[tid] = bi; __syncthreads();
        for (int off = 128; off > 0; off >>= 1) {
            if (tid < off) {
                float ov = red_v[tid+off]; int oi = red_i[tid+off];
                if (ov > red_v[tid] || (ov == red_v[tid] && oi < red_i[tid])) {
                    red_v[tid] = ov; red_i[tid] = oi;
                }
            }
            __syncthreads();
        }
        if (tid == 0) {
            int p = red_i[0];
            g_sel[b*Ss + 1 + it] = p + 1;
            sc[p] = -2.0f;   // scores positive; exclude
        }
        __syncthreads();
    }
}

// ---------------- gather selected x rows (float4) ----------------
__global__ void gather_kernel(const float* __restrict__ x) {
    int s = blockIdx.x, b = blockIdx.y;
    int tok = g_sel[b*Ss + s];
    const float4* src = (const float4*)(x + ((long)b*Nn + tok)*Cc);
    float4* dst = (float4*)(g_qloc + ((long)b*Ss + s)*Cc);
    for (int c = threadIdx.x; c < Cc/4; c += blockDim.x) dst[c] = src[c];
}

// ================= TF32 tensor-core NT GEMM (3xTF32 compensated) ==========
// C[M,N] = A[M,K] @ B[N,K]^T + bias.  N%64==0, K%16==0 required.
// Block 128x64, BK=16, 8 warps (4m x 2n), warp tile 32x32 (2x4 m16n8 frags).

__device__ __forceinline__ void tf32_split(float x, unsigned& hi, unsigned& lo) {
    unsigned h;
    asm("cvt.rna.tf32.f32 %0, %1;" : "=r"(h) : "f"(x));
    float hf = __uint_as_float(h);
    float r = x - hf;
    unsigned l;
    asm("cvt.rna.tf32.f32 %0, %1;" : "=r"(l) : "f"(r));
    hi = h; lo = l;
}

#define MMA_TF32(d, a, b)                                                     \
    asm volatile("mma.sync.aligned.m16n8k8.row.col.f32.tf32.tf32.f32 "        \
        "{%0,%1,%2,%3}, {%4,%5,%6,%7}, {%8,%9}, {%0,%1,%2,%3};"               \
        : "+f"(d[0]), "+f"(d[1]), "+f"(d[2]), "+f"(d[3])                      \
        : "r"(a[0]), "r"(a[1]), "r"(a[2]), "r"(a[3]), "r"(b[0]), "r"(b[1]))

__global__ __launch_bounds__(256)
void gemm_tf32_nt(const float* __restrict__ A, const float* __restrict__ Bm,
                  float* __restrict__ C, int M, int N, int K,
                  const float* __restrict__ bias)
{
    __shared__ unsigned Ah[128][20];
    __shared__ unsigned Al[128][20];
    __shared__ unsigned Bh[64][20];
    __shared__ unsigned Bl[64][20];

    int tid = threadIdx.x;
    int lane = tid & 31, wid = tid >> 5;
    int wm = wid & 3, wn = wid >> 2;          // warp grid 4(m) x 2(n)
    int m0 = blockIdx.y * 128, n0 = blockIdx.x * 64;
    int wmb = wm * 32, wnb = wn * 32;
    int lq = lane >> 2;                        // 0..7
    int lr = lane & 3;                         // 0..3

    float acc[2][4][4];
    #pragma unroll
    for (int i = 0; i < 2; i++)
        #pragma unroll
        for (int j = 0; j < 4; j++)
            #pragma unroll
            for (int c = 0; c < 4; c++) acc[i][j][c] = 0.f;

    for (int k0 = 0; k0 < K; k0 += 16) {
        // A tile 128x16 = 512 float4; 2 per thread
        #pragma unroll
        for (int i = 0; i < 2; i++) {
            int idx = tid + i*256;
            int m = idx >> 2, kq = (idx & 3) * 4;
            int gm = m0 + m;
            float4 v = (gm < M) ? *(const float4*)(A + (size_t)gm*K + k0 + kq)
                                : make_float4(0.f,0.f,0.f,0.f);
            unsigned h, l;
            tf32_split(v.x, h, l); Ah[m][kq+0] = h; Al[m][kq+0] = l;
            tf32_split(v.y, h, l); Ah[m][kq+1] = h; Al[m][kq+1] = l;
            tf32_split(v.z, h, l); Ah[m][kq+2] = h; Al[m][kq+2] = l;
            tf32_split(v.w, h, l); Ah[m][kq+3] = h; Al[m][kq+3] = l;
        }
        // B tile 64x16 = 256 float4; 1 per thread (N%64==0 -> in bounds)
        {
            int n = tid >> 2, kq = (tid & 3) * 4;
            float4 v = *(const float4*)(Bm + (size_t)(n0 + n)*K + k0 + kq);
            unsigned h, l;
            tf32_split(v.x, h, l); Bh[n][kq+0] = h; Bl[n][kq+0] = l;
            tf32_split(v.y, h, l); Bh[n][kq+1] = h; Bl[n][kq+1] = l;
            tf32_split(v.z, h, l); Bh[n][kq+2] = h; Bl[n][kq+2] = l;
            tf32_split(v.w, h, l); Bh[n][kq+3] = h; Bl[n][kq+3] = l;
        }
        __syncthreads();
        #pragma unroll
        for (int ks = 0; ks < 16; ks += 8) {
            unsigned ah[2][4], al[2][4];
            #pragma unroll
            for (int fm = 0; fm < 2; fm++) {
                int mr = wmb + fm*16 + lq;
                ah[fm][0] = Ah[mr  ][ks+lr  ]; al[fm][0] = Al[mr  ][ks+lr  ];
                ah[fm][1] = Ah[mr+8][ks+lr  ]; al[fm][1] = Al[mr+8][ks+lr  ];
                ah[fm][2] = Ah[mr  ][ks+lr+4]; al[fm][2] = Al[mr  ][ks+lr+4];
                ah[fm][3] = Ah[mr+8][ks+lr+4]; al[fm][3] = Al[mr+8][ks+lr+4];
            }
            unsigned bh[4][2], bl[4][2];
            #pragma unroll
            for (int fn = 0; fn < 4; fn++) {
                int nc = wnb + fn*8 + lq;
                bh[fn][0] = Bh[nc][ks+lr  ];  bl[fn][0] = Bl[nc][ks+lr  ];
                bh[fn][1] = Bh[nc][ks+lr+4];  bl[fn][1] = Bl[nc][ks+lr+4];
            }
            #pragma unroll
            for (int fm = 0; fm < 2; fm++)
                #pragma unroll
                for (int fn = 0; fn < 4; fn++) {
                    MMA_TF32(acc[fm][fn], ah[fm], bh[fn]);
                    MMA_TF32(acc[fm][fn], ah[fm], bl[fn]);
                    MMA_TF32(acc[fm][fn], al[fm], bh[fn]);
                }
        }
        __syncthreads();
    }

    // epilogue
    #pragma unroll
    for (int fm = 0; fm < 2; fm++) {
        int r0 = m0 + wmb + fm*16 + lq;
        #pragma unroll
        for (int fn = 0; fn < 4; fn++) {
            int cb = n0 + wnb + fn*8 + lr*2;
            float b0 = bias ? bias[cb]   : 0.f;
            float b1 = bias ? bias[cb+1] : 0.f;
            if (r0 < M) {
                C[(size_t)r0*N + cb]   = acc[fm][fn][0] + b0;
                C[(size_t)r0*N + cb+1] = acc[fm][fn][1] + b1;
            }
            if (r0 + 8 < M) {
                C[(size_t)(r0+8)*N + cb]   = acc[fm][fn][2] + b0;
                C[(size_t)(r0+8)*N + cb+1] = acc[fm][fn][3] + b1;
            }
        }
    }
}

// ---------------- generic batched-strided GEMM (FFMA; small shapes) -------
template<bool BT>
__global__ void gemm128_kernel(const float* __restrict__ Ag,
                               const float* __restrict__ Bg,
                               float* __restrict__ Cg,
                               int M, int Ncols, int K,
                               int lda, int ldb, int ldc,
                               long sAb, long sAh, long sBb, long sBh,
                               long sCb, long sCh, int Hdim,
                               const float* __restrict__ bias, float alpha)
{
    const int BM = 128, BN = 128, BK = 16;
    int z  = blockIdx.z;
    int zb = z / Hdim, zh = z % Hdim;
    const float* A = Ag + zb*sAb + zh*sAh;
    const float* Bp = Bg + zb*sBb + zh*sBh;
    float* C = Cg + zb*sCb + zh*sCh;
    int m0 = blockIdx.y * BM;
    int n0 = blockIdx.x * BN;

    __shared__ float As[BK][BM];
    __shared__ float Bs[BK][BN];

    int tid = threadIdx.x;
    int tx = tid & 15, ty = tid >> 4;
    float acc[8][8];
    #pragma unroll
    for (int i = 0; i < 8; i++)
        #pragma unroll
        for (int j = 0; j < 8; j++) acc[i][j] = 0.f;

    for (int k0 = 0; k0 < K; k0 += BK) {
        #pragma unroll
        for (int idx = tid; idx < BM*BK; idx += 256) {
            int mm = idx >> 4, kk = idx & 15;
            int gm = m0 + mm, gk = k0 + kk;
            float v = 0.f;
            if (gm < M && gk < K) v = A[(long)gm*lda + gk];
            As[kk][mm] = v;
        }
        #pragma unroll
        for (int idx = tid; idx < BN*BK; idx += 256) {
            int nn, kk;
            if (BT) { nn = idx >> 4; kk = idx & 15; }
            else    { kk = idx >> 7; nn = idx & 127; }
            int gn = n0 + nn, gk = k0 + kk;
            float v = 0.f;
            if (gn < Ncols && gk < K)
                v = BT ? Bp[(long)gn*ldb + gk] : Bp[(long)gk*ldb + gn];
            Bs[kk][nn] = v;
        }
        __syncthreads();
        #pragma unroll
        for (int kk = 0; kk < BK; kk++) {
            float a[8], bb[8];
            #pragma unroll
            for (int i = 0; i < 8; i++) a[i] = As[kk][ty*8 + i];
            #pragma unroll
            for (int j = 0; j < 8; j++) bb[j] = Bs[kk][tx*8 + j];
            #pragma unroll
            for (int i = 0; i < 8; i++)
                #pragma unroll
                for (int j = 0; j < 8; j++) acc[i][j] += a[i]*bb[j];
        }
        __syncthreads();
    }

    #pragma unroll
    for (int i = 0; i < 8; i++) {
        int gm = m0 + ty*8 + i;
        if (gm >= M) continue;
        #pragma unroll
        for (int j = 0; j < 8; j++) {
            int gn = n0 + tx*8 + j;
            if (gn >= Ncols) continue;
            float v = acc[i][j]*alpha;
            if (bias) v += bias[gn];
            C[(long)gm*ldc + gn] = v;
        }
    }
}

// ---------------- softmax over rows of length N ----------------
__global__ void softmax_kernel(float* __restrict__ P) {
    long row = blockIdx.x;
    float* d = P + row*(long)Nn;
    int tid = threadIdx.x;
    __shared__ float red[256];

    float mx = -INFINITY;
    for (int i = tid; i < Nn; i += 256) { float v = d[i]; mx = v > mx ? v : mx; }
    red[tid] = mx; __syncthreads();
    for (int off = 128; off > 0; off >>= 1) {
        if (tid < off && red[tid+off] > red[tid]) red[tid] = red[tid+off];
        __syncthreads();
    }
    mx = red[0]; __syncthreads();

    float sum = 0.f;
    for (int i = tid; i < Nn; i += 256) {
        float e = expf(d[i] - mx);
        d[i] = e;
        sum += e;
    }
    red[tid] = sum; __syncthreads();
    for (int off = 128; off > 0; off >>= 1) {
        if (tid < off) red[tid] += red[tid+off];
        __syncthreads();
    }
    float inv = 1.0f / red[0];
    for (int i = tid; i < Nn; i += 256) d[i] *= inv;
}

// ---------------- zero + scatter ----------------
__global__ void zero_kernel(float4* __restrict__ p, long n4) {
    long i = (long)blockIdx.x * blockDim.x + threadIdx.x;
    if (i < n4) p[i] = make_float4(0.f, 0.f, 0.f, 0.f);
}

__global__ void scatter_kernel(float* __restrict__ out) {
    int s = blockIdx.x, b = blockIdx.y;
    int tok = g_sel[b*Ss + s];
    const float4* src = (const float4*)(g_o + ((long)b*Ss + s)*Cc);
    float4* dst = (float4*)(out + ((long)b*Nn + tok)*Cc);
    for (int c = threadIdx.x; c < Cc/4; c += blockDim.x) dst[c] = src[c];
}

// ---------------- launch ----------------
extern "C" void kernel_launch(void* const* d_in, const int* in_sizes, int n_in,
                              void* d_out, int out_size) {
    const float* x  = (const float*)d_in[0];
    const float* AH = (const float*)d_in[1];
    const float* Wq = (const float*)d_in[2];
    const float* bq = (const float*)d_in[3];
    const float* Wk = (const float*)d_in[4];
    const float* bk = (const float*)d_in[5];
    const float* Wv = (const float*)d_in[6];
    const float* bv = (const float*)d_in[7];
    const float* Wo = (const float*)d_in[8];
    const float* bo = (const float*)d_in[9];
    float* out = (float*)d_out;

    float *pk, *pv, *pqloc, *pq, *pav, *po, *pattn_s, *pE, *pe2, *pr1, *pr2;
    cudaGetSymbolAddress((void**)&pk,      g_k);
    cudaGetSymbolAddress((void**)&pv,      g_v);
    cudaGetSymbolAddress((void**)&pqloc,   g_qloc);
    cudaGetSymbolAddress((void**)&pq,      g_q);
    cudaGetSymbolAddress((void**)&pav,     g_av);
    cudaGetSymbolAddress((void**)&po,      g_o);
    cudaGetSymbolAddress((void**)&pattn_s, g_attn_scratch);
    cudaGetSymbolAddress((void**)&pE,      g_E);
    cudaGetSymbolAddress((void**)&pe2,     g_e2);
    cudaGetSymbolAddress((void**)&pr1,     g_r1);
    cudaGetSymbolAddress((void**)&pr2,     g_r2);

    float* attnP = (out_size >= OUT1 + OUT2) ? (out + OUT1) : pattn_s;

    // ---- rollout (row-0 factorization; VF=2 interleaved score dot) ----
    build_E_kernel<<<dim3(Nn, Bb), 256>>>(AH);
    build_e2_kernel<<<dim3((Nn+255)/256, Bb), 256>>>(AH);
    rowsum_xla_kernel<<<Bb*Nn, 1024>>>(pE, pr1, Bb*Nn);   // r1 rows of E
    rowsum_xla_kernel<<<Bb, 1024>>>(pe2, pr2, Bb);        // r2 rows of e2
    v2_kernel<<<dim3((Nn+255)/256, Bb), 256>>>();
    score_chain_kernel<<<dim3((Nn+127)/128, Bb), 128>>>();
    topk_kernel<<<Bb, 256>>>();
    gather_kernel<<<dim3(Ss, Bb), 256>>>(x);

    // ---- projections on tensor cores (3xTF32) ----
    {
        dim3 g(Cc/64, (Bb*Nn + 127)/128);
        gemm_tf32_nt<<<g, 256>>>(x, Wk, pk, Bb*Nn, Cc, Cc, bk);
        gemm_tf32_nt<<<g, 256>>>(x, Wv, pv, Bb*Nn, Cc, Cc, bv);
    }
    {
        dim3 g(Cc/64, (Bb*Ss + 127)/128);
        gemm_tf32_nt<<<g, 256>>>(pqloc, Wq, pq, Bb*Ss, Cc, Cc, bq);
    }

    // ---- logits: attn[b,h,s,n] = SCALE * q . k  (batched NT) ----
    {
        dim3 g((Nn+127)/128, 1, Bb*Hh);
        gemm128_kernel<true><<<g, 256>>>(pq, pk, attnP,
                                         Ss, Nn, Dd,
                                         Cc, Cc, Nn,
                                         (long)Ss*Cc, (long)Dd,
                                         (long)Nn*Cc, (long)Dd,
                                         (long)Hh*Ss*Nn, (long)Ss*Nn, Hh,
                                         nullptr, SCALE_F);
    }

    // ---- softmax rows (this IS the attn_weights output) ----
    softmax_kernel<<<Bb*Hh*Ss, 256>>>(attnP);

    // ---- AV: out[b,h,s,d] = P @ V  (batched NN) ----
    {
        dim3 g(1, 1, Bb*Hh);
        gemm128_kernel<false><<<g, 256>>>(attnP, pv, pav,
                                          Ss, Dd, Nn,
                                          Nn, Cc, Cc,
                                          (long)Hh*Ss*Nn, (long)Ss*Nn,
                                          (long)Nn*Cc, (long)Dd,
                                          (long)Ss*Cc, (long)Dd, Hh,
                                          nullptr, 1.0f);
    }

    // ---- output projection on tensor cores ----
    {
        dim3 g(Cc/64, (Bb*Ss + 127)/128);
        gemm_tf32_nt<<<g, 256>>>(pav, Wo, po, Bb*Ss, Cc, Cc, bo);
    }

    // ---- scatter into zeroed token grid ----
    zero_kernel<<<(OUT1/4 + 255)/256, 256>>>((float4*)out, (long)(OUT1/4));
    scatter_kernel<<<dim3(Ss, Bb), 256>>>(out);
}